// round 9
// baseline (speedup 1.0000x reference)
#include <cuda_runtime.h>
#include <cuda_bf16.h>
#include <cstddef>

// Problem constants
#define NCH 16
#define ND  64
#define NH  96
#define NW  96
#define PLANE (NH*NW)            // 9216
#define CH_STRIDE (ND*NH*NW)     // 589824
#define KOUT 8
#define NTILE 36                 // 2 z-halves * 6 h-tiles * 3 w-tiles

// Tile geometry: 32 wide x 16 tall output, 256 threads, 4 CTAs/SM
#define TBH 16                   // output tile height
#define XROWS 20                 // extended rows (TBH+4)
#define XCOLS 36                 // extended cols (32+4)
#define NPAIR 360                // XROWS * XCOLS/2
#define GROWS 18                 // grad rows (TBH+2)
#define GSTR  36                 // grad row stride (34 used)

typedef unsigned long long u64;

// ---- f32x2 packed helpers (sm_103a) ----
__device__ __forceinline__ u64 pk2(float a, float b) {
    u64 r; asm("mov.b64 %0,{%1,%2};" : "=l"(r) : "f"(a), "f"(b)); return r;
}
__device__ __forceinline__ void upk2(u64 v, float& a, float& b) {
    asm("mov.b64 {%0,%1},%2;" : "=f"(a), "=f"(b) : "l"(v));
}
__device__ __forceinline__ u64 add2(u64 a, u64 b) {
    u64 r; asm("add.rn.f32x2 %0,%1,%2;" : "=l"(r) : "l"(a), "l"(b)); return r;
}
__device__ __forceinline__ u64 mul2(u64 a, u64 b) {
    u64 r; asm("mul.rn.f32x2 %0,%1,%2;" : "=l"(r) : "l"(a), "l"(b)); return r;
}
__device__ __forceinline__ u64 fma2(u64 a, u64 b, u64 c) {
    u64 r; asm("fma.rn.f32x2 %0,%1,%2,%3;" : "=l"(r) : "l"(a), "l"(b), "l"(c)); return r;
}

__device__ float g_part[NCH * NTILE];
__device__ int   g_idx[KOUT];

__global__ __launch_bounds__(256, 4) void harris_kernel(const float* __restrict__ x) {
    __shared__ float2 AB[XROWS * 38];     // (A, BZ) interleaved, row stride 38
    __shared__ float  GX[GROWS * GSTR];
    __shared__ float  GY[GROWS * GSTR];
    __shared__ float  GZ[GROWS * GSTR];
    __shared__ float  RED[8];

    const int tid   = threadIdx.x;
    const int c     = blockIdx.z >> 1;
    const int zhalf = blockIdx.z & 1;
    const int h0    = blockIdx.y * TBH;
    const int w0    = blockIdx.x * 32;
    const float* xc = x + (size_t)c * CH_STRIDE;

    const int z0 = zhalf * 32;
    const int z1 = z0 + 32;
    const int s_begin = (z0 == 0) ? 0 : z0 - 1;
    const int s_end   = (z1 == ND) ? ND - 1 : z1;   // inclusive

    // ---- per-thread owned PIXEL PAIRS (even col j, j+1) of the 20x36 grid ----
    int poff[2];   // global float offset of left px (even gw), or -1 pad, -2 inactive
    int psto[2];   // AB float2 index of left px
#pragma unroll
    for (int k = 0; k < 2; k++) {
        int p = tid + k * 256;
        if (p < NPAIR) {
            int i = p / 18, m = p % 18, j = 2 * m;
            psto[k] = i*38 + j;
            int gh = h0 + i - 2, gw = w0 + j - 2;     // gw even
            poff[k] = ((unsigned)gh < (unsigned)NH && (unsigned)gw <= 94u)
                      ? gh*NW + gw : -1;
        } else { psto[k] = 0; poff[k] = -2; }
    }

    // x-depth ring per pair
    float2 xm[2], x0r[2];
#pragma unroll
    for (int k = 0; k < 2; k++) {
        xm[k] = make_float2(0.f, 0.f); x0r[k] = make_float2(0.f, 0.f);
        if (poff[k] >= 0) {
            const float2* base = reinterpret_cast<const float2*>(xc + poff[k]);
            if (s_begin - 1 >= 0) xm[k] = base[(size_t)(s_begin-1)*(PLANE/2)];
            x0r[k] = base[(size_t)s_begin*(PLANE/2)];
        }
    }

    // fused-stage ownership: 1 row fr, 2 horizontal px (cols fj, fj+1)
    const int fr = tid >> 4;          // 0..15
    const int fj = (tid & 15) * 2;    // 0..30 even

    u64 A1[6], A2[6];
    const u64 ZERO2 = pk2(0.f, 0.f);
#pragma unroll
    for (int k = 0; k < 6; k++) { A1[k] = ZERO2; A2[k] = ZERO2; }
    u64 hsum2 = ZERO2;
    const u64 C1v  = pk2(1.f/19683.f, 1.f/19683.f);   // 1/27^3
    const u64 C2v  = pk2(0.04f/729.f, 0.04f/729.f);   // k/27^2
    const u64 NEG1 = pk2(-1.f, -1.f);

#define SUB2(a, b) fma2((b), NEG1, (a))

// st1: write slice T into AB (loads x(T+1) pair inline)
#define DO_ST1(T) do {                                                         \
    int t_ = (T);                                                              \
    _Pragma("unroll")                                                          \
    for (int k = 0; k < 2; k++) {                                              \
        if (k == 0 || tid < NPAIR - 256) {                                     \
            float2 xp = make_float2(0.f, 0.f);                                 \
            if (poff[k] >= 0 && t_ + 1 < ND)                                   \
                xp = reinterpret_cast<const float2*>(xc + poff[k])             \
                         [(size_t)(t_+1)*(PLANE/2)];                           \
            float4 st;                                                         \
            st.x = xm[k].x + x0r[k].x + xp.x;  st.y = xp.x - xm[k].x;          \
            st.z = xm[k].y + x0r[k].y + xp.y;  st.w = xp.y - xm[k].y;          \
            *reinterpret_cast<float4*>(AB + psto[k]) = st;                     \
            xm[k] = x0r[k]; x0r[k] = xp;                                       \
        }                                                                      \
    }                                                                          \
} while (0)

// stage2: 2x2 grad outputs per thread; 9x17 = 153 active threads
#define DO_ST2() do {                                                          \
    if (tid < 153) {                                                           \
        int i0 = (tid / 17) * 2, j0 = (tid % 17) * 2;                          \
        float Av[4][4], Bv[4][4];                                              \
        _Pragma("unroll")                                                      \
        for (int r = 0; r < 4; r++) {                                          \
            const float4* p = reinterpret_cast<const float4*>(AB + ((i0+r)*38 + j0)); \
            float4 u = p[0], v = p[1];                                         \
            Av[r][0]=u.x; Bv[r][0]=u.y; Av[r][1]=u.z; Bv[r][1]=u.w;            \
            Av[r][2]=v.x; Bv[r][2]=v.y; Av[r][3]=v.z; Bv[r][3]=v.w;            \
        }                                                                      \
        float hd[4][2], h121[4][2], rs[4][2];                                  \
        _Pragma("unroll")                                                      \
        for (int r = 0; r < 4; r++) {                                          \
            hd[r][0]   = Av[r][2] - Av[r][0];                                  \
            hd[r][1]   = Av[r][3] - Av[r][1];                                  \
            h121[r][0] = Av[r][0] + 2.f*Av[r][1] + Av[r][2];                   \
            h121[r][1] = Av[r][1] + 2.f*Av[r][2] + Av[r][3];                   \
            rs[r][0]   = Bv[r][0] + Bv[r][1] + Bv[r][2];                       \
            rs[r][1]   = Bv[r][1] + Bv[r][2] + Bv[r][3];                       \
        }                                                                      \
        _Pragma("unroll")                                                      \
        for (int rr = 0; rr < 2; rr++) {                                       \
            int go = (i0+rr)*GSTR + j0;                                        \
            float gx0 = hd[rr][0] + 2.f*hd[rr+1][0] + hd[rr+2][0];             \
            float gx1 = hd[rr][1] + 2.f*hd[rr+1][1] + hd[rr+2][1];             \
            float gy0 = h121[rr+2][0] - h121[rr][0];                           \
            float gy1 = h121[rr+2][1] - h121[rr][1];                           \
            float gz0 = rs[rr][0] + rs[rr+1][0] + rs[rr+2][0];                 \
            float gz1 = rs[rr][1] + rs[rr+1][1] + rs[rr+2][1];                 \
            *reinterpret_cast<float2*>(GX + go) = make_float2(gx0, gx1);       \
            *reinterpret_cast<float2*>(GY + go) = make_float2(gy0, gy1);       \
            *reinterpret_cast<float2*>(GZ + go) = make_float2(gz0, gz1);       \
        }                                                                      \
    }                                                                          \
} while (0)

    // ---- prologue: st1(s_begin), st2(s_begin) ----
    DO_ST1(s_begin);
    __syncthreads();
    DO_ST2();
    __syncthreads();

    // ================= main loop =================
    for (int s = s_begin; s <= s_end; s++) {
        const bool more = (s < s_end);

        // ---------- phase A: prefetch x(s+2), fused st3+4(s), st1-store(s+1) ----------
        float2 xpv[2];
        if (more) {
#pragma unroll
            for (int k = 0; k < 2; k++) {
                xpv[k] = make_float2(0.f, 0.f);
                if ((k == 0 || tid < NPAIR - 256) && poff[k] >= 0 && s + 2 < ND)
                    xpv[k] = reinterpret_cast<const float2*>(xc + poff[k])
                                 [(size_t)(s+2)*(PLANE/2)];
            }
        }

        // fused stage3+4 on slice s: packed column-sum products (fma2 on raw loads)
        {
            u64 accA[6], accB[6];
#pragma unroll
            for (int k = 0; k < 6; k++) { accA[k] = ZERO2; accB[k] = ZERO2; }
#pragma unroll
            for (int ri = 0; ri < 3; ri++) {
                int b = (fr + ri) * GSTR + fj;
                u64 xa = *reinterpret_cast<const u64*>(GX + b);
                u64 xb = *reinterpret_cast<const u64*>(GX + b + 2);
                u64 ya = *reinterpret_cast<const u64*>(GY + b);
                u64 yb = *reinterpret_cast<const u64*>(GY + b + 2);
                u64 za = *reinterpret_cast<const u64*>(GZ + b);
                u64 zb = *reinterpret_cast<const u64*>(GZ + b + 2);
                accA[0] = fma2(xa, xa, accA[0]);  accB[0] = fma2(xb, xb, accB[0]);
                accA[1] = fma2(ya, ya, accA[1]);  accB[1] = fma2(yb, yb, accB[1]);
                accA[2] = fma2(za, za, accA[2]);  accB[2] = fma2(zb, zb, accB[2]);
                accA[3] = fma2(xa, ya, accA[3]);  accB[3] = fma2(xb, yb, accB[3]);
                accA[4] = fma2(xa, za, accA[4]);  accB[4] = fma2(xb, zb, accB[4]);
                accA[5] = fma2(ya, za, accA[5]);  accB[5] = fma2(yb, zb, accB[5]);
            }
            // horizontal combine: lanes (P0,P1),(P2,P3) -> l = P0+P1+P2, r = P1+P2+P3
            u64 cur[6];
#pragma unroll
            for (int k = 0; k < 6; k++) {
                float a0, a1, b0, b1;
                upk2(accA[k], a0, a1);
                upk2(accB[k], b0, b1);
                float m = a1 + b0;
                cur[k] = pk2(a0 + m, m + b1);
            }

            int d = s - 1;
            if (d >= z0) {
                u64 sxx = add2(A2[0], cur[0]);
                u64 syy = add2(A2[1], cur[1]);
                u64 szz = add2(A2[2], cur[2]);
                u64 sxy = add2(A2[3], cur[3]);
                u64 sxz = add2(A2[4], cur[4]);
                u64 syz = add2(A2[5], cur[5]);
                u64 m1  = SUB2(mul2(syy, szz), mul2(syz, syz));
                u64 m2  = SUB2(mul2(sxy, szz), mul2(syz, sxz));
                u64 m3  = SUB2(mul2(sxy, syz), mul2(syy, sxz));
                u64 det = SUB2(fma2(sxx, m1, mul2(sxz, m3)), mul2(sxy, m2));
                u64 tr  = add2(add2(sxx, syy), szz);
                u64 h   = SUB2(mul2(det, C1v), mul2(mul2(tr, tr), C2v));
                hsum2 = add2(hsum2, h);
            }
#pragma unroll
            for (int k = 0; k < 6; k++) { A2[k] = add2(A1[k], cur[k]); A1[k] = cur[k]; }
        }

        // st1 stores for slice s+1 (consumes prefetched xpv)
        if (more) {
#pragma unroll
            for (int k = 0; k < 2; k++) {
                if (k == 0 || tid < NPAIR - 256) {
                    float4 st;
                    st.x = xm[k].x + x0r[k].x + xpv[k].x;  st.y = xpv[k].x - xm[k].x;
                    st.z = xm[k].y + x0r[k].y + xpv[k].y;  st.w = xpv[k].y - xm[k].y;
                    *reinterpret_cast<float4*>(AB + psto[k]) = st;
                    xm[k] = x0r[k]; x0r[k] = xpv[k];
                }
            }
        }
        __syncthreads();

        // ---------- phase B: st2(s+1) ----------
        if (more) {
            DO_ST2();
        }
        __syncthreads();
    }

    // tail: output depth ND-1 (slice at ND contributes 0)
    if (z1 == ND) {
        u64 sxx = A2[0], syy = A2[1], szz = A2[2];
        u64 sxy = A2[3], sxz = A2[4], syz = A2[5];
        u64 m1  = SUB2(mul2(syy, szz), mul2(syz, syz));
        u64 m2  = SUB2(mul2(sxy, szz), mul2(syz, sxz));
        u64 m3  = SUB2(mul2(sxy, syz), mul2(syy, sxz));
        u64 det = SUB2(fma2(sxx, m1, mul2(sxz, m3)), mul2(sxy, m2));
        u64 tr  = add2(add2(sxx, syy), szz);
        u64 h   = SUB2(mul2(det, C1v), mul2(mul2(tr, tr), C2v));
        hsum2 = add2(hsum2, h);
    }

    // ---- reduction -> g_part (non-atomic, deterministic) ----
    float ha, hb;
    upk2(hsum2, ha, hb);
    float hsum = ha + hb;
#pragma unroll
    for (int o = 16; o > 0; o >>= 1)
        hsum += __shfl_down_sync(0xffffffffu, hsum, o);
    if ((tid & 31) == 0) RED[tid >> 5] = hsum;
    __syncthreads();
    if (tid < 32) {
        float v = (tid < 8) ? RED[tid] : 0.f;
#pragma unroll
        for (int o = 4; o > 0; o >>= 1)
            v += __shfl_down_sync(0xffffffffu, v, o);
        if (tid == 0) {
            int tile_id = zhalf * 18 + blockIdx.y * 3 + blockIdx.x;
            g_part[c * NTILE + tile_id] = v;
        }
    }
#undef SUB2
#undef DO_ST1
#undef DO_ST2
}

__global__ void topk_kernel() {
    __shared__ double vsh[NCH];
    int t = threadIdx.x;
    if (t < NCH) {
        double s = 0.0;
        for (int i = 0; i < NTILE; i++) s += (double)g_part[t * NTILE + i];
        vsh[t] = s;
    }
    __syncthreads();
    if (t == 0) {
        bool used[NCH];
        for (int i = 0; i < NCH; i++) used[i] = false;
        for (int k = 0; k < KOUT; k++) {
            int bi = 0; double bv = -1e300; bool found = false;
            for (int i = 0; i < NCH; i++) {
                if (!used[i] && (!found || vsh[i] > bv)) { bv = vsh[i]; bi = i; found = true; }
            }
            used[bi] = true;
            g_idx[k] = bi;
        }
    }
}

// Gather: 256 threads x 4 float4; 1024 float4 per block; 1152 blocks.
__global__ __launch_bounds__(256) void gather_kernel(const float* __restrict__ x,
                                                     float* __restrict__ out) {
    const int per_ch_v = CH_STRIDE / 4;          // 147456
    const int chunks_per_ch = per_ch_v / 1024;   // 144
    int k = blockIdx.x / chunks_per_ch;
    int chunk = blockIdx.x - k * chunks_per_ch;
    int c = g_idx[k];
    const float4* src = reinterpret_cast<const float4*>(x + (size_t)c * CH_STRIDE);
    float4* dst = reinterpret_cast<float4*>(out) + (size_t)k * per_ch_v;
    int base = chunk * 1024 + threadIdx.x;
    float4 v0 = src[base];
    float4 v1 = src[base + 256];
    float4 v2 = src[base + 512];
    float4 v3 = src[base + 768];
    dst[base]       = v0;
    dst[base + 256] = v1;
    dst[base + 512] = v2;
    dst[base + 768] = v3;
}

extern "C" void kernel_launch(void* const* d_in, const int* in_sizes, int n_in,
                              void* d_out, int out_size) {
    const float* x = (const float*)d_in[0];
    float* out = (float*)d_out;

    dim3 grid(3, 6, NCH * 2);   // 576 blocks, 4 CTAs/SM, one wave
    harris_kernel<<<grid, 256>>>(x);
    topk_kernel<<<1, 32>>>();
    const int gather_blocks = KOUT * ((CH_STRIDE / 4) / 1024);  // 1152
    gather_kernel<<<gather_blocks, 256>>>(x, out);
}

// round 10
// speedup vs baseline: 1.1144x; 1.1144x over previous
#include <cuda_runtime.h>
#include <cuda_bf16.h>
#include <cstddef>

// Problem constants
#define NCH 16
#define ND  64
#define NH  96
#define NW  96
#define PLANE (NH*NW)            // 9216
#define CH_STRIDE (ND*NH*NW)     // 589824
#define KOUT 8
#define NTILE 36                 // 2 z-halves * 6 h-tiles * 3 w-tiles

// Tile geometry: 32 wide x 16 tall output, 256 threads, 4 CTAs/SM
#define TBH 16                   // output tile height
#define XROWS 20                 // extended rows (TBH+4)
#define XCOLS 36                 // extended cols (32+4)
#define NPAIR 360                // XROWS * XCOLS/2
#define GROWS 18                 // grad rows (TBH+2)
#define GSTR  36                 // grad row stride (34 used)

typedef unsigned long long u64;

// ---- f32x2 packed helpers (sm_103a) ----
__device__ __forceinline__ u64 pk2(float a, float b) {
    u64 r; asm("mov.b64 %0,{%1,%2};" : "=l"(r) : "f"(a), "f"(b)); return r;
}
__device__ __forceinline__ void upk2(u64 v, float& a, float& b) {
    asm("mov.b64 {%0,%1},%2;" : "=f"(a), "=f"(b) : "l"(v));
}
__device__ __forceinline__ u64 add2(u64 a, u64 b) {
    u64 r; asm("add.rn.f32x2 %0,%1,%2;" : "=l"(r) : "l"(a), "l"(b)); return r;
}
__device__ __forceinline__ u64 mul2(u64 a, u64 b) {
    u64 r; asm("mul.rn.f32x2 %0,%1,%2;" : "=l"(r) : "l"(a), "l"(b)); return r;
}
__device__ __forceinline__ u64 fma2(u64 a, u64 b, u64 c) {
    u64 r; asm("fma.rn.f32x2 %0,%1,%2,%3;" : "=l"(r) : "l"(a), "l"(b), "l"(c)); return r;
}

__device__ float g_part[NCH * NTILE];
__device__ int   g_idx[KOUT];

__global__ __launch_bounds__(256, 4) void harris_kernel(const float* __restrict__ x) {
    __shared__ float2 AB[XROWS * 38];     // (A, BZ) interleaved, row stride 38
    __shared__ float  GX[GROWS * GSTR];
    __shared__ float  GY[GROWS * GSTR];
    __shared__ float  GZ[GROWS * GSTR];
    __shared__ float  RED[8];

    const int tid   = threadIdx.x;
    const int c     = blockIdx.z >> 1;
    const int zhalf = blockIdx.z & 1;
    const int h0    = blockIdx.y * TBH;
    const int w0    = blockIdx.x * 32;
    const float* xc = x + (size_t)c * CH_STRIDE;

    const int z0 = zhalf * 32;
    const int z1 = z0 + 32;
    const int s_begin = (z0 == 0) ? 0 : z0 - 1;
    const int s_end   = (z1 == ND) ? ND - 1 : z1;   // inclusive

    // ---- per-thread owned PIXEL PAIRS (even col j, j+1) of the 20x36 grid ----
    int poff[2];   // global float offset of left px (even gw), or -1 pad, -2 inactive
    int psto[2];   // AB float2 index of left px
#pragma unroll
    for (int k = 0; k < 2; k++) {
        int p = tid + k * 256;
        if (p < NPAIR) {
            int i = p / 18, m = p % 18, j = 2 * m;
            psto[k] = i*38 + j;
            int gh = h0 + i - 2, gw = w0 + j - 2;     // gw even
            poff[k] = ((unsigned)gh < (unsigned)NH && (unsigned)gw <= 94u)
                      ? gh*NW + gw : -1;
        } else { psto[k] = 0; poff[k] = -2; }
    }

    // x-depth ring per pair
    float2 xm[2], x0r[2];
#pragma unroll
    for (int k = 0; k < 2; k++) {
        xm[k] = make_float2(0.f, 0.f); x0r[k] = make_float2(0.f, 0.f);
        if (poff[k] >= 0) {
            const float2* base = reinterpret_cast<const float2*>(xc + poff[k]);
            if (s_begin - 1 >= 0) xm[k] = base[(size_t)(s_begin-1)*(PLANE/2)];
            x0r[k] = base[(size_t)s_begin*(PLANE/2)];
        }
    }

    // fused-stage ownership: 1 row fr, 2 horizontal px (cols fj, fj+1)
    const int fr = tid >> 4;          // 0..15
    const int fj = (tid & 15) * 2;    // 0..30 even

    u64 A1[6], A2[6];
    const u64 ZERO2 = pk2(0.f, 0.f);
#pragma unroll
    for (int k = 0; k < 6; k++) { A1[k] = ZERO2; A2[k] = ZERO2; }
    u64 hsum2 = ZERO2;
    const u64 C1v  = pk2(1.f/19683.f, 1.f/19683.f);   // 1/27^3
    const u64 C2v  = pk2(0.04f/729.f, 0.04f/729.f);   // k/27^2
    const u64 NEG1 = pk2(-1.f, -1.f);

#define SUB2(a, b) fma2((b), NEG1, (a))

// st1: write slice T into AB (loads x(T+1) pair inline)
#define DO_ST1(T) do {                                                         \
    int t_ = (T);                                                              \
    _Pragma("unroll")                                                          \
    for (int k = 0; k < 2; k++) {                                              \
        if (k == 0 || tid < NPAIR - 256) {                                     \
            float2 xp = make_float2(0.f, 0.f);                                 \
            if (poff[k] >= 0 && t_ + 1 < ND)                                   \
                xp = reinterpret_cast<const float2*>(xc + poff[k])             \
                         [(size_t)(t_+1)*(PLANE/2)];                           \
            float4 st;                                                         \
            st.x = xm[k].x + x0r[k].x + xp.x;  st.y = xp.x - xm[k].x;          \
            st.z = xm[k].y + x0r[k].y + xp.y;  st.w = xp.y - xm[k].y;          \
            *reinterpret_cast<float4*>(AB + psto[k]) = st;                     \
            xm[k] = x0r[k]; x0r[k] = xp;                                       \
        }                                                                      \
    }                                                                          \
} while (0)

// stage2: 3 grad rows x 2 cols per thread; 6x17 = 102 active threads.
// Rolling 3-row window over 5 AB rows (r%3 slots fold under full unroll).
#define DO_ST2() do {                                                          \
    if (tid < 102) {                                                           \
        int i0 = (tid / 17) * 3, j0 = (tid % 17) * 2;                          \
        float hdw[3][2], h1w[3][2], rsw[3][2];                                 \
        _Pragma("unroll")                                                      \
        for (int r = 0; r < 5; r++) {                                          \
            const float4* p = reinterpret_cast<const float4*>(AB + ((i0+r)*38 + j0)); \
            float4 u = p[0], v = p[1];                                         \
            int w = r % 3;                                                     \
            hdw[w][0] = v.x - u.x;                                             \
            hdw[w][1] = v.z - u.z;                                             \
            h1w[w][0] = u.x + 2.f*u.z + v.x;                                   \
            h1w[w][1] = u.z + 2.f*v.x + v.z;                                   \
            rsw[w][0] = u.y + u.w + v.y;                                       \
            rsw[w][1] = u.w + v.y + v.w;                                       \
            if (r >= 2) {                                                      \
                int rr = r - 2;                                                \
                int a = rr % 3, b2 = (rr+1) % 3, c2 = r % 3;                   \
                int go = (i0+rr)*GSTR + j0;                                    \
                float gx0 = hdw[a][0] + 2.f*hdw[b2][0] + hdw[c2][0];           \
                float gx1 = hdw[a][1] + 2.f*hdw[b2][1] + hdw[c2][1];           \
                float gy0 = h1w[c2][0] - h1w[a][0];                            \
                float gy1 = h1w[c2][1] - h1w[a][1];                            \
                float gz0 = rsw[a][0] + rsw[b2][0] + rsw[c2][0];               \
                float gz1 = rsw[a][1] + rsw[b2][1] + rsw[c2][1];               \
                *reinterpret_cast<float2*>(GX + go) = make_float2(gx0, gx1);   \
                *reinterpret_cast<float2*>(GY + go) = make_float2(gy0, gy1);   \
                *reinterpret_cast<float2*>(GZ + go) = make_float2(gz0, gz1);   \
            }                                                                  \
        }                                                                      \
    }                                                                          \
} while (0)

    // ---- prologue: st1(s_begin), st2(s_begin) ----
    DO_ST1(s_begin);
    __syncthreads();
    DO_ST2();
    __syncthreads();

    // ================= main loop =================
    for (int s = s_begin; s <= s_end; s++) {
        const bool more = (s < s_end);

        // ---------- phase A: prefetch x(s+2), fused st3+4(s), st1-store(s+1) ----------
        float2 xpv[2];
        if (more) {
#pragma unroll
            for (int k = 0; k < 2; k++) {
                xpv[k] = make_float2(0.f, 0.f);
                if ((k == 0 || tid < NPAIR - 256) && poff[k] >= 0 && s + 2 < ND)
                    xpv[k] = reinterpret_cast<const float2*>(xc + poff[k])
                                 [(size_t)(s+2)*(PLANE/2)];
            }
        }

        // fused stage3+4 on slice s: 1 row x 2 cols, float2 G reads (R8 form)
        {
            float l[6], rr[6];
#pragma unroll
            for (int k = 0; k < 6; k++) { l[k] = 0.f; rr[k] = 0.f; }
#pragma unroll
            for (int ri = 0; ri < 3; ri++) {
                int b = (fr + ri) * GSTR + fj;
                float2 xa = *reinterpret_cast<const float2*>(GX + b);
                float2 xb = *reinterpret_cast<const float2*>(GX + b + 2);
                float2 ya = *reinterpret_cast<const float2*>(GY + b);
                float2 yb = *reinterpret_cast<const float2*>(GY + b + 2);
                float2 za = *reinterpret_cast<const float2*>(GZ + b);
                float2 zb = *reinterpret_cast<const float2*>(GZ + b + 2);
                float X[4] = {xa.x, xa.y, xb.x, xb.y};
                float Y[4] = {ya.x, ya.y, yb.x, yb.y};
                float Z[4] = {za.x, za.y, zb.x, zb.y};
#pragma unroll
                for (int cc = 0; cc < 4; cc++) {
                    if (cc < 3) {
                        l[0] = fmaf(X[cc],X[cc],l[0]);
                        l[1] = fmaf(Y[cc],Y[cc],l[1]);
                        l[2] = fmaf(Z[cc],Z[cc],l[2]);
                        l[3] = fmaf(X[cc],Y[cc],l[3]);
                        l[4] = fmaf(X[cc],Z[cc],l[4]);
                        l[5] = fmaf(Y[cc],Z[cc],l[5]);
                    }
                    if (cc > 0) {
                        rr[0] = fmaf(X[cc],X[cc],rr[0]);
                        rr[1] = fmaf(Y[cc],Y[cc],rr[1]);
                        rr[2] = fmaf(Z[cc],Z[cc],rr[2]);
                        rr[3] = fmaf(X[cc],Y[cc],rr[3]);
                        rr[4] = fmaf(X[cc],Z[cc],rr[4]);
                        rr[5] = fmaf(Y[cc],Z[cc],rr[5]);
                    }
                }
            }
            u64 cur[6];
#pragma unroll
            for (int k = 0; k < 6; k++) cur[k] = pk2(l[k], rr[k]);

            int d = s - 1;
            if (d >= z0) {
                u64 sxx = add2(A2[0], cur[0]);
                u64 syy = add2(A2[1], cur[1]);
                u64 szz = add2(A2[2], cur[2]);
                u64 sxy = add2(A2[3], cur[3]);
                u64 sxz = add2(A2[4], cur[4]);
                u64 syz = add2(A2[5], cur[5]);
                u64 m1  = SUB2(mul2(syy, szz), mul2(syz, syz));
                u64 m2  = SUB2(mul2(sxy, szz), mul2(syz, sxz));
                u64 m3  = SUB2(mul2(sxy, syz), mul2(syy, sxz));
                u64 det = SUB2(fma2(sxx, m1, mul2(sxz, m3)), mul2(sxy, m2));
                u64 tr  = add2(add2(sxx, syy), szz);
                u64 h   = SUB2(mul2(det, C1v), mul2(mul2(tr, tr), C2v));
                hsum2 = add2(hsum2, h);
            }
#pragma unroll
            for (int k = 0; k < 6; k++) { A2[k] = add2(A1[k], cur[k]); A1[k] = cur[k]; }
        }

        // st1 stores for slice s+1 (consumes prefetched xpv)
        if (more) {
#pragma unroll
            for (int k = 0; k < 2; k++) {
                if (k == 0 || tid < NPAIR - 256) {
                    float4 st;
                    st.x = xm[k].x + x0r[k].x + xpv[k].x;  st.y = xpv[k].x - xm[k].x;
                    st.z = xm[k].y + x0r[k].y + xpv[k].y;  st.w = xpv[k].y - xm[k].y;
                    *reinterpret_cast<float4*>(AB + psto[k]) = st;
                    xm[k] = x0r[k]; x0r[k] = xpv[k];
                }
            }
        }
        __syncthreads();

        // ---------- phase B: st2(s+1) ----------
        if (more) {
            DO_ST2();
        }
        __syncthreads();
    }

    // tail: output depth ND-1 (slice at ND contributes 0)
    if (z1 == ND) {
        u64 sxx = A2[0], syy = A2[1], szz = A2[2];
        u64 sxy = A2[3], sxz = A2[4], syz = A2[5];
        u64 m1  = SUB2(mul2(syy, szz), mul2(syz, syz));
        u64 m2  = SUB2(mul2(sxy, szz), mul2(syz, sxz));
        u64 m3  = SUB2(mul2(sxy, syz), mul2(syy, sxz));
        u64 det = SUB2(fma2(sxx, m1, mul2(sxz, m3)), mul2(sxy, m2));
        u64 tr  = add2(add2(sxx, syy), szz);
        u64 h   = SUB2(mul2(det, C1v), mul2(mul2(tr, tr), C2v));
        hsum2 = add2(hsum2, h);
    }

    // ---- reduction -> g_part (non-atomic, deterministic) ----
    float ha, hb;
    upk2(hsum2, ha, hb);
    float hsum = ha + hb;
#pragma unroll
    for (int o = 16; o > 0; o >>= 1)
        hsum += __shfl_down_sync(0xffffffffu, hsum, o);
    if ((tid & 31) == 0) RED[tid >> 5] = hsum;
    __syncthreads();
    if (tid < 32) {
        float v = (tid < 8) ? RED[tid] : 0.f;
#pragma unroll
        for (int o = 4; o > 0; o >>= 1)
            v += __shfl_down_sync(0xffffffffu, v, o);
        if (tid == 0) {
            int tile_id = zhalf * 18 + blockIdx.y * 3 + blockIdx.x;
            g_part[c * NTILE + tile_id] = v;
        }
    }
#undef SUB2
#undef DO_ST1
#undef DO_ST2
}

__global__ void topk_kernel() {
    __shared__ double vsh[NCH];
    int t = threadIdx.x;
    if (t < NCH) {
        double s = 0.0;
        for (int i = 0; i < NTILE; i++) s += (double)g_part[t * NTILE + i];
        vsh[t] = s;
    }
    __syncthreads();
    if (t == 0) {
        bool used[NCH];
        for (int i = 0; i < NCH; i++) used[i] = false;
        for (int k = 0; k < KOUT; k++) {
            int bi = 0; double bv = -1e300; bool found = false;
            for (int i = 0; i < NCH; i++) {
                if (!used[i] && (!found || vsh[i] > bv)) { bv = vsh[i]; bi = i; found = true; }
            }
            used[bi] = true;
            g_idx[k] = bi;
        }
    }
}

// Gather: 256 threads x 4 float4; 1024 float4 per block; 1152 blocks.
__global__ __launch_bounds__(256) void gather_kernel(const float* __restrict__ x,
                                                     float* __restrict__ out) {
    const int per_ch_v = CH_STRIDE / 4;          // 147456
    const int chunks_per_ch = per_ch_v / 1024;   // 144
    int k = blockIdx.x / chunks_per_ch;
    int chunk = blockIdx.x - k * chunks_per_ch;
    int c = g_idx[k];
    const float4* src = reinterpret_cast<const float4*>(x + (size_t)c * CH_STRIDE);
    float4* dst = reinterpret_cast<float4*>(out) + (size_t)k * per_ch_v;
    int base = chunk * 1024 + threadIdx.x;
    float4 v0 = src[base];
    float4 v1 = src[base + 256];
    float4 v2 = src[base + 512];
    float4 v3 = src[base + 768];
    dst[base]       = v0;
    dst[base + 256] = v1;
    dst[base + 512] = v2;
    dst[base + 768] = v3;
}

extern "C" void kernel_launch(void* const* d_in, const int* in_sizes, int n_in,
                              void* d_out, int out_size) {
    const float* x = (const float*)d_in[0];
    float* out = (float*)d_out;

    dim3 grid(3, 6, NCH * 2);   // 576 blocks, 4 CTAs/SM, one wave
    harris_kernel<<<grid, 256>>>(x);
    topk_kernel<<<1, 32>>>();
    const int gather_blocks = KOUT * ((CH_STRIDE / 4) / 1024);  // 1152
    gather_kernel<<<gather_blocks, 256>>>(x, out);
}

// round 11
// speedup vs baseline: 1.1516x; 1.0333x over previous
#include <cuda_runtime.h>
#include <cuda_bf16.h>
#include <cstddef>

// Problem constants
#define NCH 16
#define ND  64
#define NH  96
#define NW  96
#define PLANE (NH*NW)            // 9216
#define CH_STRIDE (ND*NH*NW)     // 589824
#define KOUT 8
#define NTILE 36                 // 2 z-halves * 6 h-tiles * 3 w-tiles

// Tile geometry: 32 wide x 16 tall output, 256 threads, 4 CTAs/SM
#define TBH 16                   // output tile height
#define XROWS 20                 // extended rows (TBH+4)
#define XCOLS 36                 // extended cols (32+4)
#define NPAIR 360                // XROWS * XCOLS/2
#define GROWS 18                 // grad rows (TBH+2)
#define GPSTR 18                 // GXY row stride in float4 (17 pairs used)
#define GSTR  36                 // GZ row stride in floats (34 used)

typedef unsigned long long u64;

// ---- f32x2 packed helpers (sm_103a) ----
__device__ __forceinline__ u64 pk2(float a, float b) {
    u64 r; asm("mov.b64 %0,{%1,%2};" : "=l"(r) : "f"(a), "f"(b)); return r;
}
__device__ __forceinline__ void upk2(u64 v, float& a, float& b) {
    asm("mov.b64 {%0,%1},%2;" : "=f"(a), "=f"(b) : "l"(v));
}
__device__ __forceinline__ u64 add2(u64 a, u64 b) {
    u64 r; asm("add.rn.f32x2 %0,%1,%2;" : "=l"(r) : "l"(a), "l"(b)); return r;
}
__device__ __forceinline__ u64 mul2(u64 a, u64 b) {
    u64 r; asm("mul.rn.f32x2 %0,%1,%2;" : "=l"(r) : "l"(a), "l"(b)); return r;
}
__device__ __forceinline__ u64 fma2(u64 a, u64 b, u64 c) {
    u64 r; asm("fma.rn.f32x2 %0,%1,%2,%3;" : "=l"(r) : "l"(a), "l"(b), "l"(c)); return r;
}

__device__ float g_part[NCH * NTILE];
__device__ int   g_idx[KOUT];

__global__ __launch_bounds__(256, 4) void harris_kernel(const float* __restrict__ x) {
    __shared__ float2 AB[XROWS * 38];       // (A, BZ) interleaved, row stride 38
    __shared__ float4 GXY[GROWS * GPSTR];   // (gx0,gy0,gx1,gy1) per col-pair
    __shared__ float  GZ[GROWS * GSTR];
    __shared__ float  RED[8];

    const int tid   = threadIdx.x;
    const int c     = blockIdx.z >> 1;
    const int zhalf = blockIdx.z & 1;
    const int h0    = blockIdx.y * TBH;
    const int w0    = blockIdx.x * 32;
    const float* xc = x + (size_t)c * CH_STRIDE;

    const int z0 = zhalf * 32;
    const int z1 = z0 + 32;
    const int s_begin = (z0 == 0) ? 0 : z0 - 1;
    const int s_end   = (z1 == ND) ? ND - 1 : z1;   // inclusive

    // ---- per-thread owned PIXEL PAIRS (even col j, j+1) of the 20x36 grid ----
    int poff[2];   // global float offset of left px (even gw), or -1 pad, -2 inactive
    int psto[2];   // AB float2 index of left px
#pragma unroll
    for (int k = 0; k < 2; k++) {
        int p = tid + k * 256;
        if (p < NPAIR) {
            int i = p / 18, m = p % 18, j = 2 * m;
            psto[k] = i*38 + j;
            int gh = h0 + i - 2, gw = w0 + j - 2;     // gw even
            poff[k] = ((unsigned)gh < (unsigned)NH && (unsigned)gw <= 94u)
                      ? gh*NW + gw : -1;
        } else { psto[k] = 0; poff[k] = -2; }
    }

    // x-depth ring per pair
    float2 xm[2], x0r[2];
#pragma unroll
    for (int k = 0; k < 2; k++) {
        xm[k] = make_float2(0.f, 0.f); x0r[k] = make_float2(0.f, 0.f);
        if (poff[k] >= 0) {
            const float2* base = reinterpret_cast<const float2*>(xc + poff[k]);
            if (s_begin - 1 >= 0) xm[k] = base[(size_t)(s_begin-1)*(PLANE/2)];
            x0r[k] = base[(size_t)s_begin*(PLANE/2)];
        }
    }

    // fused-stage ownership: 1 row fr, 2 horizontal px (col pair p0)
    const int fr = tid >> 4;          // 0..15
    const int fp = tid & 15;          // col-pair 0..15 (cols 2*fp, 2*fp+1)

    u64 A1[6], A2[6];
    const u64 ZERO2 = pk2(0.f, 0.f);
#pragma unroll
    for (int k = 0; k < 6; k++) { A1[k] = ZERO2; A2[k] = ZERO2; }
    u64 hsum2 = ZERO2;
    const u64 C1v  = pk2(1.f/19683.f, 1.f/19683.f);   // 1/27^3
    const u64 C2v  = pk2(0.04f/729.f, 0.04f/729.f);   // k/27^2
    const u64 NEG1 = pk2(-1.f, -1.f);

#define SUB2(a, b) fma2((b), NEG1, (a))

// st1: write slice T into AB (loads x(T+1) pair inline)
#define DO_ST1(T) do {                                                         \
    int t_ = (T);                                                              \
    _Pragma("unroll")                                                          \
    for (int k = 0; k < 2; k++) {                                              \
        if (k == 0 || tid < NPAIR - 256) {                                     \
            float2 xp = make_float2(0.f, 0.f);                                 \
            if (poff[k] >= 0 && t_ + 1 < ND)                                   \
                xp = reinterpret_cast<const float2*>(xc + poff[k])             \
                         [(size_t)(t_+1)*(PLANE/2)];                           \
            float4 st;                                                         \
            st.x = xm[k].x + x0r[k].x + xp.x;  st.y = xp.x - xm[k].x;          \
            st.z = xm[k].y + x0r[k].y + xp.y;  st.w = xp.y - xm[k].y;          \
            *reinterpret_cast<float4*>(AB + psto[k]) = st;                     \
            xm[k] = x0r[k]; x0r[k] = xp;                                       \
        }                                                                      \
    }                                                                          \
} while (0)

// stage2: 3 grad rows x 2 cols per thread; 6x17 = 102 active threads.
// Rolling 3-row window over 5 AB rows; writes GXY (float4) + GZ (float2).
#define DO_ST2() do {                                                          \
    if (tid < 102) {                                                           \
        int i0 = (tid / 17) * 3, jp = tid % 17, j0 = jp * 2;                   \
        float hdw[3][2], h1w[3][2], rsw[3][2];                                 \
        _Pragma("unroll")                                                      \
        for (int r = 0; r < 5; r++) {                                          \
            const float4* p = reinterpret_cast<const float4*>(AB + ((i0+r)*38 + j0)); \
            float4 u = p[0], v = p[1];                                         \
            int w = r % 3;                                                     \
            hdw[w][0] = v.x - u.x;                                             \
            hdw[w][1] = v.z - u.z;                                             \
            h1w[w][0] = u.x + 2.f*u.z + v.x;                                   \
            h1w[w][1] = u.z + 2.f*v.x + v.z;                                   \
            rsw[w][0] = u.y + u.w + v.y;                                       \
            rsw[w][1] = u.w + v.y + v.w;                                       \
            if (r >= 2) {                                                      \
                int rr = r - 2;                                                \
                int a = rr % 3, b2 = (rr+1) % 3, c2 = r % 3;                   \
                float gx0 = hdw[a][0] + 2.f*hdw[b2][0] + hdw[c2][0];           \
                float gx1 = hdw[a][1] + 2.f*hdw[b2][1] + hdw[c2][1];           \
                float gy0 = h1w[c2][0] - h1w[a][0];                            \
                float gy1 = h1w[c2][1] - h1w[a][1];                            \
                float gz0 = rsw[a][0] + rsw[b2][0] + rsw[c2][0];               \
                float gz1 = rsw[a][1] + rsw[b2][1] + rsw[c2][1];               \
                GXY[(i0+rr)*GPSTR + jp] = make_float4(gx0, gy0, gx1, gy1);     \
                *reinterpret_cast<float2*>(GZ + (i0+rr)*GSTR + j0)             \
                    = make_float2(gz0, gz1);                                   \
            }                                                                  \
        }                                                                      \
    }                                                                          \
} while (0)

    // ---- prologue: st1(s_begin), st2(s_begin) ----
    DO_ST1(s_begin);
    __syncthreads();
    DO_ST2();
    __syncthreads();

    // ================= main loop =================
    for (int s = s_begin; s <= s_end; s++) {
        const bool more = (s < s_end);

        // ---------- phase A: prefetch x(s+2), fused st3+4(s), st1-store(s+1) ----------
        float2 xpv[2];
        if (more) {
#pragma unroll
            for (int k = 0; k < 2; k++) {
                xpv[k] = make_float2(0.f, 0.f);
                if ((k == 0 || tid < NPAIR - 256) && poff[k] >= 0 && s + 2 < ND)
                    xpv[k] = reinterpret_cast<const float2*>(xc + poff[k])
                                 [(size_t)(s+2)*(PLANE/2)];
            }
        }

        // fused stage3+4 on slice s: GXY float4 + GZ float2 reads
        {
            float l[6], rr[6];
#pragma unroll
            for (int k = 0; k < 6; k++) { l[k] = 0.f; rr[k] = 0.f; }
#pragma unroll
            for (int ri = 0; ri < 3; ri++) {
                int row = fr + ri;
                float4 q0 = GXY[row*GPSTR + fp];
                float4 q1 = GXY[row*GPSTR + fp + 1];
                int bz = row*GSTR + fp*2;
                float2 za = *reinterpret_cast<const float2*>(GZ + bz);
                float2 zb = *reinterpret_cast<const float2*>(GZ + bz + 2);
                float X[4] = {q0.x, q0.z, q1.x, q1.z};
                float Y[4] = {q0.y, q0.w, q1.y, q1.w};
                float Z[4] = {za.x, za.y, zb.x, zb.y};
#pragma unroll
                for (int cc = 0; cc < 4; cc++) {
                    if (cc < 3) {
                        l[0] = fmaf(X[cc],X[cc],l[0]);
                        l[1] = fmaf(Y[cc],Y[cc],l[1]);
                        l[2] = fmaf(Z[cc],Z[cc],l[2]);
                        l[3] = fmaf(X[cc],Y[cc],l[3]);
                        l[4] = fmaf(X[cc],Z[cc],l[4]);
                        l[5] = fmaf(Y[cc],Z[cc],l[5]);
                    }
                    if (cc > 0) {
                        rr[0] = fmaf(X[cc],X[cc],rr[0]);
                        rr[1] = fmaf(Y[cc],Y[cc],rr[1]);
                        rr[2] = fmaf(Z[cc],Z[cc],rr[2]);
                        rr[3] = fmaf(X[cc],Y[cc],rr[3]);
                        rr[4] = fmaf(X[cc],Z[cc],rr[4]);
                        rr[5] = fmaf(Y[cc],Z[cc],rr[5]);
                    }
                }
            }
            u64 cur[6];
#pragma unroll
            for (int k = 0; k < 6; k++) cur[k] = pk2(l[k], rr[k]);

            int d = s - 1;
            if (d >= z0) {
                u64 sxx = add2(A2[0], cur[0]);
                u64 syy = add2(A2[1], cur[1]);
                u64 szz = add2(A2[2], cur[2]);
                u64 sxy = add2(A2[3], cur[3]);
                u64 sxz = add2(A2[4], cur[4]);
                u64 syz = add2(A2[5], cur[5]);
                u64 m1  = SUB2(mul2(syy, szz), mul2(syz, syz));
                u64 m2  = SUB2(mul2(sxy, szz), mul2(syz, sxz));
                u64 m3  = SUB2(mul2(sxy, syz), mul2(syy, sxz));
                u64 det = SUB2(fma2(sxx, m1, mul2(sxz, m3)), mul2(sxy, m2));
                u64 tr  = add2(add2(sxx, syy), szz);
                u64 h   = SUB2(mul2(det, C1v), mul2(mul2(tr, tr), C2v));
                hsum2 = add2(hsum2, h);
            }
#pragma unroll
            for (int k = 0; k < 6; k++) { A2[k] = add2(A1[k], cur[k]); A1[k] = cur[k]; }
        }

        // st1 stores for slice s+1 (consumes prefetched xpv)
        if (more) {
#pragma unroll
            for (int k = 0; k < 2; k++) {
                if (k == 0 || tid < NPAIR - 256) {
                    float4 st;
                    st.x = xm[k].x + x0r[k].x + xpv[k].x;  st.y = xpv[k].x - xm[k].x;
                    st.z = xm[k].y + x0r[k].y + xpv[k].y;  st.w = xpv[k].y - xm[k].y;
                    *reinterpret_cast<float4*>(AB + psto[k]) = st;
                    xm[k] = x0r[k]; x0r[k] = xpv[k];
                }
            }
        }
        __syncthreads();

        // ---------- phase B: st2(s+1) ----------
        if (more) {
            DO_ST2();
        }
        __syncthreads();
    }

    // tail: output depth ND-1 (slice at ND contributes 0)
    if (z1 == ND) {
        u64 sxx = A2[0], syy = A2[1], szz = A2[2];
        u64 sxy = A2[3], sxz = A2[4], syz = A2[5];
        u64 m1  = SUB2(mul2(syy, szz), mul2(syz, syz));
        u64 m2  = SUB2(mul2(sxy, szz), mul2(syz, sxz));
        u64 m3  = SUB2(mul2(sxy, syz), mul2(syy, sxz));
        u64 det = SUB2(fma2(sxx, m1, mul2(sxz, m3)), mul2(sxy, m2));
        u64 tr  = add2(add2(sxx, syy), szz);
        u64 h   = SUB2(mul2(det, C1v), mul2(mul2(tr, tr), C2v));
        hsum2 = add2(hsum2, h);
    }

    // ---- reduction -> g_part (non-atomic, deterministic) ----
    float ha, hb;
    upk2(hsum2, ha, hb);
    float hsum = ha + hb;
#pragma unroll
    for (int o = 16; o > 0; o >>= 1)
        hsum += __shfl_down_sync(0xffffffffu, hsum, o);
    if ((tid & 31) == 0) RED[tid >> 5] = hsum;
    __syncthreads();
    if (tid < 32) {
        float v = (tid < 8) ? RED[tid] : 0.f;
#pragma unroll
        for (int o = 4; o > 0; o >>= 1)
            v += __shfl_down_sync(0xffffffffu, v, o);
        if (tid == 0) {
            int tile_id = zhalf * 18 + blockIdx.y * 3 + blockIdx.x;
            g_part[c * NTILE + tile_id] = v;
        }
    }
#undef SUB2
#undef DO_ST1
#undef DO_ST2
}

__global__ void topk_kernel() {
    __shared__ double vsh[NCH];
    int t = threadIdx.x;
    if (t < NCH) {
        double s = 0.0;
        for (int i = 0; i < NTILE; i++) s += (double)g_part[t * NTILE + i];
        vsh[t] = s;
    }
    __syncthreads();
    if (t == 0) {
        bool used[NCH];
        for (int i = 0; i < NCH; i++) used[i] = false;
        for (int k = 0; k < KOUT; k++) {
            int bi = 0; double bv = -1e300; bool found = false;
            for (int i = 0; i < NCH; i++) {
                if (!used[i] && (!found || vsh[i] > bv)) { bv = vsh[i]; bi = i; found = true; }
            }
            used[bi] = true;
            g_idx[k] = bi;
        }
    }
}

// Gather: 256 threads x 4 float4; streaming hints (read-once / write-once).
__global__ __launch_bounds__(256) void gather_kernel(const float* __restrict__ x,
                                                     float* __restrict__ out) {
    const int per_ch_v = CH_STRIDE / 4;          // 147456
    const int chunks_per_ch = per_ch_v / 1024;   // 144
    int k = blockIdx.x / chunks_per_ch;
    int chunk = blockIdx.x - k * chunks_per_ch;
    int c = g_idx[k];
    const float4* src = reinterpret_cast<const float4*>(x + (size_t)c * CH_STRIDE);
    float4* dst = reinterpret_cast<float4*>(out) + (size_t)k * per_ch_v;
    int base = chunk * 1024 + threadIdx.x;
    float4 v0 = __ldcs(src + base);
    float4 v1 = __ldcs(src + base + 256);
    float4 v2 = __ldcs(src + base + 512);
    float4 v3 = __ldcs(src + base + 768);
    __stcs(dst + base,       v0);
    __stcs(dst + base + 256, v1);
    __stcs(dst + base + 512, v2);
    __stcs(dst + base + 768, v3);
}

extern "C" void kernel_launch(void* const* d_in, const int* in_sizes, int n_in,
                              void* d_out, int out_size) {
    const float* x = (const float*)d_in[0];
    float* out = (float*)d_out;

    dim3 grid(3, 6, NCH * 2);   // 576 blocks, 4 CTAs/SM, one wave
    harris_kernel<<<grid, 256>>>(x);
    topk_kernel<<<1, 32>>>();
    const int gather_blocks = KOUT * ((CH_STRIDE / 4) / 1024);  // 1152
    gather_kernel<<<gather_blocks, 256>>>(x, out);
}